// round 1
// baseline (speedup 1.0000x reference)
#include <cuda_runtime.h>

// ---------------- problem constants ----------------
#define BATCH 4
#define SEQ   8192
#define NDIM  512
#define HEADS 8
#define DH    64
#define ML    256          // landmarks
#define LP    32           // tokens per landmark
#define BH    32           // BATCH*HEADS
#define MTOK  32768        // BATCH*SEQ
#define KCONV 33

// ---------------- scratch (device globals; no allocation allowed) ----------------
__device__ float g_q[16777216];      // [BH, SEQ, DH]
__device__ float g_k[16777216];
__device__ float g_v[16777216];
__device__ float g_ql[524288];       // [BH, ML, DH]
__device__ float g_kl[524288];
__device__ float g_attn1[67108864];  // [BH, SEQ, ML]
__device__ float g_attn3[67108864];  // [BH, ML, SEQ]
__device__ float g_attn2[2097152];   // [BH, ML, ML]
__device__ float g_z0[2097152];
__device__ float g_z1[2097152];
__device__ float g_xz[2097152];
__device__ float g_t[2097152];
__device__ float g_u[2097152];
__device__ float g_a3v[524288];      // [BH, ML, DH]
__device__ float g_wm[524288];       // [BH, ML, DH]
__device__ float g_y[16777216];      // [MTOK, NDIM]  (b, n, h*64+dh)
__device__ float g_scal[2];

// ---------------- generic batched tiled GEMM ----------------
// C[M,N] = alpha * A[M,K] @ (TRANSB ? B[N,K]^T : B[K,N])  (+bias, +resid)
// batch offset: A += bz*sA; B += bz*sB; C += (bz/bdiv)*sCo + (bz%bdiv)*sCi
// splitK > 1: blockIdx.z = batch*splitK + kslice, epilogue via atomicAdd (C pre-zeroed)
template<bool TRANSB>
__global__ void gemm_kernel(const float* __restrict__ A, const float* __restrict__ B,
                            float* __restrict__ C,
                            int M, int N, int K, int lda, int ldb, int ldc,
                            long long sA, long long sB,
                            int bdiv, long long sCo, long long sCi,
                            int splitK, float alpha,
                            const float* __restrict__ bias,
                            const float* __restrict__ resid)
{
    int zz = blockIdx.z;
    int bz = zz / splitK;
    int ks = zz % splitK;
    int Kc = K / splitK;
    int kbeg = ks * Kc, kend = kbeg + Kc;

    A += (long long)bz * sA;
    B += (long long)bz * sB;
    C += (long long)(bz / bdiv) * sCo + (long long)(bz % bdiv) * sCi;

    __shared__ float As[16][68];
    __shared__ float Bs[16][68];

    const int tid = threadIdx.x;
    const int tx = tid & 15, ty = tid >> 4;
    const int m0 = blockIdx.y * 64;
    const int n0 = blockIdx.x * 64;

    float acc[4][4] = {};

    for (int k0 = kbeg; k0 < kend; k0 += 16) {
        #pragma unroll
        for (int i = tid; i < 1024; i += 256) {
            int m = i >> 4, kk = i & 15;
            int gm = m0 + m, gk = k0 + kk;
            float v = 0.f;
            if (gm < M && gk < K) v = A[(long long)gm * lda + gk];
            As[kk][m] = v;
        }
        #pragma unroll
        for (int i = tid; i < 1024; i += 256) {
            float v = 0.f;
            if (TRANSB) {
                int n = i >> 4, kk = i & 15;
                int gn = n0 + n, gk = k0 + kk;
                if (gn < N && gk < K) v = B[(long long)gn * ldb + gk];
                Bs[kk][n] = v;
            } else {
                int kk = i >> 6, n = i & 63;
                int gk = k0 + kk, gn = n0 + n;
                if (gk < K && gn < N) v = B[(long long)gk * ldb + gn];
                Bs[kk][n] = v;
            }
        }
        __syncthreads();
        #pragma unroll
        for (int kk = 0; kk < 16; kk++) {
            float a[4], bb[4];
            #pragma unroll
            for (int i = 0; i < 4; i++) a[i] = As[kk][ty * 4 + i];
            #pragma unroll
            for (int j = 0; j < 4; j++) bb[j] = Bs[kk][tx * 4 + j];
            #pragma unroll
            for (int i = 0; i < 4; i++)
                #pragma unroll
                for (int j = 0; j < 4; j++)
                    acc[i][j] = fmaf(a[i], bb[j], acc[i][j]);
        }
        __syncthreads();
    }

    #pragma unroll
    for (int i = 0; i < 4; i++) {
        int gm = m0 + ty * 4 + i;
        if (gm >= M) continue;
        #pragma unroll
        for (int j = 0; j < 4; j++) {
            int gn = n0 + tx * 4 + j;
            if (gn >= N) continue;
            float v = alpha * acc[i][j];
            long long off = (long long)gm * ldc + gn;
            if (splitK > 1) {
                atomicAdd(&C[off], v);
            } else {
                if (bias)  v += bias[gn];
                if (resid) v += resid[off];
                C[off] = v;
            }
        }
    }
}

// ---------------- fused QKV GEMM: x[MTOK,512] @ w_qkv[512,1536] -> q/k/v [BH,SEQ,DH] ----------------
__global__ void qkv_gemm_kernel(const float* __restrict__ A, const float* __restrict__ B)
{
    __shared__ float As[16][68];
    __shared__ float Bs[16][68];

    const int tid = threadIdx.x;
    const int tx = tid & 15, ty = tid >> 4;
    const int m0 = blockIdx.y * 64;
    const int n0 = blockIdx.x * 64;
    const int lda = 512, ldb = 1536;

    float acc[4][4] = {};

    for (int k0 = 0; k0 < 512; k0 += 16) {
        #pragma unroll
        for (int i = tid; i < 1024; i += 256) {
            int m = i >> 4, kk = i & 15;
            As[kk][m] = A[(long long)(m0 + m) * lda + k0 + kk];
        }
        #pragma unroll
        for (int i = tid; i < 1024; i += 256) {
            int kk = i >> 6, n = i & 63;
            Bs[kk][n] = B[(long long)(k0 + kk) * ldb + n0 + n];
        }
        __syncthreads();
        #pragma unroll
        for (int kk = 0; kk < 16; kk++) {
            float a[4], bb[4];
            #pragma unroll
            for (int i = 0; i < 4; i++) a[i] = As[kk][ty * 4 + i];
            #pragma unroll
            for (int j = 0; j < 4; j++) bb[j] = Bs[kk][tx * 4 + j];
            #pragma unroll
            for (int i = 0; i < 4; i++)
                #pragma unroll
                for (int j = 0; j < 4; j++)
                    acc[i][j] = fmaf(a[i], bb[j], acc[i][j]);
        }
        __syncthreads();
    }

    #pragma unroll
    for (int i = 0; i < 4; i++) {
        int gm = m0 + ty * 4 + i;          // token index b*SEQ + n
        int b = gm >> 13, n = gm & 8191;
        #pragma unroll
        for (int j = 0; j < 4; j++) {
            int gn = n0 + tx * 4 + j;      // col in [0,1536)
            int sec = gn >> 9;
            int rem = gn & 511;
            int h = rem >> 6, dh = rem & 63;
            long long off = (((long long)(b * HEADS + h)) * SEQ + n) * DH + dh;
            float v = acc[i][j];
            if (sec == 0)      g_q[off] = v * 0.125f;   // d^-0.5 = 1/8
            else if (sec == 1) g_k[off] = v;
            else               g_v[off] = v;
        }
    }
}

// ---------------- landmark mean pooling ----------------
__global__ void pool_kernel()
{
    long long idx = (long long)blockIdx.x * 256 + threadIdx.x;   // 524288 total
    if (idx >= 524288LL) return;
    int dh = idx & 63;
    int mi = (int)((idx >> 6) & 255);
    int bh = (int)(idx >> 14);
    const float* q = g_q + ((long long)bh * SEQ + mi * LP) * DH + dh;
    const float* k = g_k + ((long long)bh * SEQ + mi * LP) * DH + dh;
    float sq = 0.f, sk = 0.f;
    #pragma unroll
    for (int j = 0; j < LP; j++) { sq += q[j * DH]; sk += k[j * DH]; }
    g_ql[idx] = sq * (1.f / LP);
    g_kl[idx] = sk * (1.f / LP);
}

// ---------------- row softmax (one block per row, row cached in shared) ----------------
__global__ void softmax_kernel(float* __restrict__ x, int L)
{
    extern __shared__ float sh[];
    __shared__ float red[8];
    __shared__ float bval;
    long long row = blockIdx.x;
    float* p = x + row * (long long)L;
    int tid = threadIdx.x;

    float m = -1e30f;
    for (int i = tid; i < L; i += 256) { float v = p[i]; sh[i] = v; m = fmaxf(m, v); }
    #pragma unroll
    for (int o = 16; o; o >>= 1) m = fmaxf(m, __shfl_xor_sync(0xffffffffu, m, o));
    if ((tid & 31) == 0) red[tid >> 5] = m;
    __syncthreads();
    if (tid == 0) { float mm = red[0]; for (int i = 1; i < 8; i++) mm = fmaxf(mm, red[i]); bval = mm; }
    __syncthreads();
    m = bval;

    float s = 0.f;
    for (int i = tid; i < L; i += 256) { float e = __expf(sh[i] - m); sh[i] = e; s += e; }
    #pragma unroll
    for (int o = 16; o; o >>= 1) s += __shfl_xor_sync(0xffffffffu, s, o);
    if ((tid & 31) == 0) red[tid >> 5] = s;
    __syncthreads();
    if (tid == 0) { float ss = 0.f; for (int i = 0; i < 8; i++) ss += red[i]; bval = ss; }
    __syncthreads();
    float inv = 1.f / bval;
    for (int i = tid; i < L; i += 256) p[i] = sh[i] * inv;
}

// ---------------- pinv scale: global max row-sum and col-sum of attn2 ----------------
__global__ void scale_init_kernel() { if (threadIdx.x < 2) g_scal[threadIdx.x] = 0.f; }

__global__ void pinv_scale_kernel()
{
    int bz = blockIdx.x;         // 32 batches
    int j = threadIdx.x;         // 256
    const float* p = g_attn2 + (long long)bz * 65536;
    float rs = 0.f, cs = 0.f;
    for (int i = 0; i < 256; i++) { rs += p[j * 256 + i]; cs += p[i * 256 + j]; }
    atomicMax((int*)&g_scal[0], __float_as_int(rs));   // max over row sums  ("col" in ref)
    atomicMax((int*)&g_scal[1], __float_as_int(cs));   // max over col sums  ("row" in ref)
}

// ---------------- z init: z = attn2^T / (s0*s1) ----------------
__global__ void zinit_kernel()
{
    long long idx = (long long)blockIdx.x * 256 + threadIdx.x;   // 2097152 total
    if (idx >= 2097152LL) return;
    float inv = 1.f / (g_scal[0] * g_scal[1]);
    int c = (int)(idx & 255);
    int r = (int)((idx >> 8) & 255);
    long long bz = idx >> 16;
    g_z0[idx] = g_attn2[(bz << 16) + ((long long)c << 8) + r] * inv;
}

// ---------------- out = a*I - in (elementwise, in-place safe) ----------------
__global__ void aiminus_kernel(const float* __restrict__ in, float* __restrict__ out, float a)
{
    long long idx = (long long)blockIdx.x * 256 + threadIdx.x;
    if (idx >= 2097152LL) return;
    int c = (int)(idx & 255);
    int r = (int)((idx >> 8) & 255);
    float v = -in[idx];
    if (r == c) v += a;
    out[idx] = v;
}

// ---------------- zero fill ----------------
__global__ void zero_kernel(float* __restrict__ p, long long n)
{
    long long idx = (long long)blockIdx.x * 256 + threadIdx.x;
    if (idx < n) p[idx] = 0.f;
}

// ---------------- depthwise conv residual (adds into g_y) ----------------
__global__ void conv_res_kernel(const float* __restrict__ convw)
{
    __shared__ float vt[96][64];
    __shared__ float wsh[KCONV];
    int bh = blockIdx.y;
    int h = bh & 7, b = bh >> 3;
    int n0 = blockIdx.x * 64;
    int tid = threadIdx.x;
    if (tid < KCONV) wsh[tid] = convw[h * KCONV + tid];
    const float* vbase = g_v + (long long)bh * SEQ * DH;
    for (int i = tid; i < 96 * 64; i += 256) {
        int r = i >> 6, dh = i & 63;
        int n = n0 + r - 16;
        vt[r][dh] = (n >= 0 && n < SEQ) ? vbase[(long long)n * DH + dh] : 0.f;
    }
    __syncthreads();
    float* ybase = g_y + ((long long)b * SEQ + n0) * NDIM + h * DH;
    for (int o = tid; o < 64 * 64; o += 256) {
        int r = o >> 6, dh = o & 63;
        float s = 0.f;
        #pragma unroll
        for (int t = 0; t < KCONV; t++) s = fmaf(wsh[t], vt[r + t][dh], s);
        ybase[(long long)r * NDIM + dh] += s;
    }
}

// ---------------- host orchestration ----------------
static float* sym(const void* p) { void* a = nullptr; cudaGetSymbolAddress(&a, p); return (float*)a; }

extern "C" void kernel_launch(void* const* d_in, const int* in_sizes, int n_in,
                              void* d_out, int out_size)
{
    const float* x      = (const float*)d_in[0];
    const float* w_qkv  = (const float*)d_in[1];
    const float* w_out  = (const float*)d_in[2];
    const float* b_out  = (const float*)d_in[3];
    const float* conv_w = (const float*)d_in[4];
    float* out = (float*)d_out;

    float* p_q     = sym(g_q);
    float* p_k     = sym(g_k);
    float* p_v     = sym(g_v);
    float* p_ql    = sym(g_ql);
    float* p_kl    = sym(g_kl);
    float* p_a1    = sym(g_attn1);
    float* p_a3    = sym(g_attn3);
    float* p_a2    = sym(g_attn2);
    float* p_z0    = sym(g_z0);
    float* p_z1    = sym(g_z1);
    float* p_xz    = sym(g_xz);
    float* p_t     = sym(g_t);
    float* p_u     = sym(g_u);
    float* p_a3v   = sym(g_a3v);
    float* p_wm    = sym(g_wm);
    float* p_y     = sym(g_y);

    const long long BIG = 1LL << 40;
    const int UNI = 1 << 30;   // bdiv for uniform batch C stride

    // 1. QKV projection (scatter to [BH,SEQ,DH], q scaled)
    qkv_gemm_kernel<<<dim3(24, 512, 1), 256>>>(x, w_qkv);

    // 2. landmark pooling
    pool_kernel<<<2048, 256>>>();

    // 3. attn1 logits = q @ kl^T : [BH, SEQ, ML]
    gemm_kernel<true><<<dim3(4, 128, BH), 256>>>(
        p_q, p_kl, p_a1, SEQ, ML, DH, DH, DH, ML,
        (long long)SEQ * DH, (long long)ML * DH, UNI, 0, (long long)SEQ * ML,
        1, 1.f, nullptr, nullptr);
    softmax_kernel<<<BH * SEQ, 256, ML * 4>>>(p_a1, ML);

    // 4. attn2 logits = ql @ kl^T : [BH, ML, ML]
    gemm_kernel<true><<<dim3(4, 4, BH), 256>>>(
        p_ql, p_kl, p_a2, ML, ML, DH, DH, DH, ML,
        (long long)ML * DH, (long long)ML * DH, UNI, 0, (long long)ML * ML,
        1, 1.f, nullptr, nullptr);
    softmax_kernel<<<BH * ML, 256, ML * 4>>>(p_a2, ML);

    // 5. attn3 logits = ql @ k^T : [BH, ML, SEQ]
    gemm_kernel<true><<<dim3(128, 4, BH), 256>>>(
        p_ql, p_k, p_a3, ML, SEQ, DH, DH, DH, SEQ,
        (long long)ML * DH, (long long)SEQ * DH, UNI, 0, (long long)ML * SEQ,
        1, 1.f, nullptr, nullptr);
    softmax_kernel<<<BH * ML, 256, SEQ * 4>>>(p_a3, SEQ);

    // 6. Moore-Penrose init
    scale_init_kernel<<<1, 32>>>();
    pinv_scale_kernel<<<BH, 256>>>();
    zinit_kernel<<<8192, 256>>>();

    // 7. Newton-Schulz iterations
    float* zc = p_z0;
    float* zn = p_z1;
    for (int it = 0; it < 6; it++) {
        // xz = attn2 @ z
        gemm_kernel<false><<<dim3(4, 4, BH), 256>>>(
            p_a2, zc, p_xz, ML, ML, ML, ML, ML, ML,
            65536LL, 65536LL, UNI, 0, 65536LL, 1, 1.f, nullptr, nullptr);
        // t = 7I - xz
        aiminus_kernel<<<8192, 256>>>(p_xz, p_t, 7.f);
        // u = xz @ t
        gemm_kernel<false><<<dim3(4, 4, BH), 256>>>(
            p_xz, p_t, p_u, ML, ML, ML, ML, ML, ML,
            65536LL, 65536LL, UNI, 0, 65536LL, 1, 1.f, nullptr, nullptr);
        // u = 15I - u
        aiminus_kernel<<<8192, 256>>>(p_u, p_u, 15.f);
        // t = xz @ u
        gemm_kernel<false><<<dim3(4, 4, BH), 256>>>(
            p_xz, p_u, p_t, ML, ML, ML, ML, ML, ML,
            65536LL, 65536LL, UNI, 0, 65536LL, 1, 1.f, nullptr, nullptr);
        // t = 13I - t
        aiminus_kernel<<<8192, 256>>>(p_t, p_t, 13.f);
        // zn = 0.25 * z @ t
        gemm_kernel<false><<<dim3(4, 4, BH), 256>>>(
            zc, p_t, zn, ML, ML, ML, ML, ML, ML,
            65536LL, 65536LL, UNI, 0, 65536LL, 1, 0.25f, nullptr, nullptr);
        float* tmp = zc; zc = zn; zn = tmp;
    }

    // 8. a3v = attn3 @ v : [BH, ML, DH], split-K=16 over K=8192
    zero_kernel<<<2048, 256>>>(p_a3v, 524288LL);
    gemm_kernel<false><<<dim3(1, 4, BH * 16), 256>>>(
        p_a3, p_v, p_a3v, ML, DH, SEQ, SEQ, DH, DH,
        (long long)ML * SEQ, (long long)SEQ * DH, UNI, 0, (long long)ML * DH,
        16, 1.f, nullptr, nullptr);

    // 9. wm = z @ a3v : [BH, ML, DH]
    gemm_kernel<false><<<dim3(1, 4, BH), 256>>>(
        zc, p_a3v, p_wm, ML, DH, ML, ML, DH, DH,
        65536LL, (long long)ML * DH, UNI, 0, (long long)ML * DH,
        1, 1.f, nullptr, nullptr);

    // 10. y = attn1 @ wm, scattered into [b, n, h*64+dh] layout (ldc=512)
    gemm_kernel<false><<<dim3(1, 128, BH), 256>>>(
        p_a1, p_wm, p_y, SEQ, DH, ML, ML, DH, NDIM,
        (long long)SEQ * ML, (long long)ML * DH,
        HEADS, (long long)SEQ * NDIM, (long long)DH,
        1, 1.f, nullptr, nullptr);

    // 11. depthwise conv residual (adds into y)
    conv_res_kernel<<<dim3(128, BH), 256>>>(conv_w);

    // 12. out = y @ w_out + b_out + x
    gemm_kernel<false><<<dim3(8, 512, 1), 256>>>(
        p_y, w_out, out, MTOK, NDIM, NDIM, NDIM, NDIM, NDIM,
        0, 0, UNI, 0, 0, 1, 1.f, b_out, x);
}

// round 2
// speedup vs baseline: 1.3116x; 1.3116x over previous
#include <cuda_runtime.h>

// ---------------- problem constants ----------------
#define BATCH 4
#define SEQ   8192
#define NDIM  512
#define HEADS 8
#define DH    64
#define ML    256          // landmarks
#define LP    32           // tokens per landmark
#define BH    32           // BATCH*HEADS
#define MTOK  32768        // BATCH*SEQ
#define KCONV 33
#define SPLIT 8            // seq split for flash a3v

// ---------------- scratch (device globals; no allocation allowed) ----------------
__device__ float g_q[16777216];      // [BH, SEQ, DH]
__device__ float g_k[16777216];
__device__ float g_v[16777216];
__device__ float g_ql[524288];       // [BH, ML, DH]
__device__ float g_kl[524288];
__device__ float g_attn2[2097152];   // [BH, ML, ML]
__device__ float g_z0[2097152];
__device__ float g_z1[2097152];
__device__ float g_xz[2097152];
__device__ float g_t[2097152];
__device__ float g_u[2097152];
__device__ float g_a3v[524288];      // [BH, ML, DH]
__device__ float g_wm[524288];       // [BH, ML, DH]
__device__ float g_y[16777216];      // [MTOK, NDIM]  (b, n, h*64+dh)
__device__ float g_part_o[4194304];  // [SPLIT][BH*ML][DH]
__device__ float g_part_m[65536];    // [SPLIT][BH*ML]
__device__ float g_part_s[65536];
__device__ float g_scal[2];

// ---------------- generic batched tiled GEMM (kept for qkv-like shapes, wm, out) ----
template<bool TRANSB>
__global__ void gemm_kernel(const float* __restrict__ A, const float* __restrict__ B,
                            float* __restrict__ C,
                            int M, int N, int K, int lda, int ldb, int ldc,
                            long long sA, long long sB,
                            int bdiv, long long sCo, long long sCi,
                            float alpha,
                            const float* __restrict__ bias,
                            const float* __restrict__ resid)
{
    int bz = blockIdx.z;
    A += (long long)bz * sA;
    B += (long long)bz * sB;
    C += (long long)(bz / bdiv) * sCo + (long long)(bz % bdiv) * sCi;

    __shared__ float As[16][68];
    __shared__ float Bs[16][68];

    const int tid = threadIdx.x;
    const int tx = tid & 15, ty = tid >> 4;
    const int m0 = blockIdx.y * 64;
    const int n0 = blockIdx.x * 64;

    float acc[4][4] = {};

    for (int k0 = 0; k0 < K; k0 += 16) {
        #pragma unroll
        for (int i = tid; i < 1024; i += 256) {
            int m = i >> 4, kk = i & 15;
            int gm = m0 + m, gk = k0 + kk;
            float v = 0.f;
            if (gm < M && gk < K) v = A[(long long)gm * lda + gk];
            As[kk][m] = v;
        }
        #pragma unroll
        for (int i = tid; i < 1024; i += 256) {
            float v = 0.f;
            if (TRANSB) {
                int n = i >> 4, kk = i & 15;
                int gn = n0 + n, gk = k0 + kk;
                if (gn < N && gk < K) v = B[(long long)gn * ldb + gk];
                Bs[kk][n] = v;
            } else {
                int kk = i >> 6, n = i & 63;
                int gk = k0 + kk, gn = n0 + n;
                if (gk < K && gn < N) v = B[(long long)gk * ldb + gn];
                Bs[kk][n] = v;
            }
        }
        __syncthreads();
        #pragma unroll
        for (int kk = 0; kk < 16; kk++) {
            float a[4], bb[4];
            #pragma unroll
            for (int i = 0; i < 4; i++) a[i] = As[kk][ty * 4 + i];
            #pragma unroll
            for (int j = 0; j < 4; j++) bb[j] = Bs[kk][tx * 4 + j];
            #pragma unroll
            for (int i = 0; i < 4; i++)
                #pragma unroll
                for (int j = 0; j < 4; j++)
                    acc[i][j] = fmaf(a[i], bb[j], acc[i][j]);
        }
        __syncthreads();
    }

    #pragma unroll
    for (int i = 0; i < 4; i++) {
        int gm = m0 + ty * 4 + i;
        if (gm >= M) continue;
        #pragma unroll
        for (int j = 0; j < 4; j++) {
            int gn = n0 + tx * 4 + j;
            if (gn >= N) continue;
            float v = alpha * acc[i][j];
            long long off = (long long)gm * ldc + gn;
            if (bias)  v += bias[gn];
            if (resid) v += resid[off];
            C[off] = v;
        }
    }
}

// ---------------- fixed 256x256x256 batched GEMM with dual-output epilogue ----------
// C = alpha * A@B (if C != null);  D = diag*I - alpha*A@B (if D != null)
__global__ void gemm256_kernel(const float* __restrict__ A, const float* __restrict__ B,
                               float* __restrict__ C, float* __restrict__ D,
                               float alpha, float diag)
{
    int bz = blockIdx.z;
    A += (long long)bz * 65536;
    B += (long long)bz * 65536;

    __shared__ float As[16][68];
    __shared__ float Bs[16][68];

    const int tid = threadIdx.x;
    const int tx = tid & 15, ty = tid >> 4;
    const int m0 = blockIdx.y * 64;
    const int n0 = blockIdx.x * 64;

    float acc[4][4] = {};

    for (int k0 = 0; k0 < 256; k0 += 16) {
        #pragma unroll
        for (int i = tid; i < 1024; i += 256) {
            int m = i >> 4, kk = i & 15;
            As[kk][m] = A[(m0 + m) * 256 + k0 + kk];
        }
        #pragma unroll
        for (int i = tid; i < 1024; i += 256) {
            int kk = i >> 6, n = i & 63;
            Bs[kk][n] = B[(k0 + kk) * 256 + n0 + n];
        }
        __syncthreads();
        #pragma unroll
        for (int kk = 0; kk < 16; kk++) {
            float a[4], bb[4];
            #pragma unroll
            for (int i = 0; i < 4; i++) a[i] = As[kk][ty * 4 + i];
            #pragma unroll
            for (int j = 0; j < 4; j++) bb[j] = Bs[kk][tx * 4 + j];
            #pragma unroll
            for (int i = 0; i < 4; i++)
                #pragma unroll
                for (int j = 0; j < 4; j++)
                    acc[i][j] = fmaf(a[i], bb[j], acc[i][j]);
        }
        __syncthreads();
    }

    long long base = (long long)bz * 65536;
    #pragma unroll
    for (int i = 0; i < 4; i++) {
        int gm = m0 + ty * 4 + i;
        #pragma unroll
        for (int j = 0; j < 4; j++) {
            int gn = n0 + tx * 4 + j;
            float v = alpha * acc[i][j];
            long long off = base + gm * 256 + gn;
            if (C) C[off] = v;
            if (D) D[off] = (gm == gn ? diag : 0.f) - v;
        }
    }
}

// ---------------- fused QKV GEMM: x[MTOK,512] @ w_qkv[512,1536] -> q/k/v [BH,SEQ,DH] ----
__global__ void qkv_gemm_kernel(const float* __restrict__ A, const float* __restrict__ B)
{
    __shared__ float As[16][68];
    __shared__ float Bs[16][68];

    const int tid = threadIdx.x;
    const int tx = tid & 15, ty = tid >> 4;
    const int m0 = blockIdx.y * 64;
    const int n0 = blockIdx.x * 64;

    float acc[4][4] = {};

    for (int k0 = 0; k0 < 512; k0 += 16) {
        #pragma unroll
        for (int i = tid; i < 1024; i += 256) {
            int m = i >> 4, kk = i & 15;
            As[kk][m] = A[(long long)(m0 + m) * 512 + k0 + kk];
        }
        #pragma unroll
        for (int i = tid; i < 1024; i += 256) {
            int kk = i >> 6, n = i & 63;
            Bs[kk][n] = B[(long long)(k0 + kk) * 1536 + n0 + n];
        }
        __syncthreads();
        #pragma unroll
        for (int kk = 0; kk < 16; kk++) {
            float a[4], bb[4];
            #pragma unroll
            for (int i = 0; i < 4; i++) a[i] = As[kk][ty * 4 + i];
            #pragma unroll
            for (int j = 0; j < 4; j++) bb[j] = Bs[kk][tx * 4 + j];
            #pragma unroll
            for (int i = 0; i < 4; i++)
                #pragma unroll
                for (int j = 0; j < 4; j++)
                    acc[i][j] = fmaf(a[i], bb[j], acc[i][j]);
        }
        __syncthreads();
    }

    #pragma unroll
    for (int i = 0; i < 4; i++) {
        int gm = m0 + ty * 4 + i;          // token index b*SEQ + n
        int b = gm >> 13, n = gm & 8191;
        #pragma unroll
        for (int j = 0; j < 4; j++) {
            int gn = n0 + tx * 4 + j;      // col in [0,1536)
            int sec = gn >> 9;
            int rem = gn & 511;
            int h = rem >> 6, dh = rem & 63;
            long long off = (((long long)(b * HEADS + h)) * SEQ + n) * DH + dh;
            float v = acc[i][j];
            if (sec == 0)      g_q[off] = v * 0.125f;
            else if (sec == 1) g_k[off] = v;
            else               g_v[off] = v;
        }
    }
}

// ---------------- landmark mean pooling ----------------
__global__ void pool_kernel()
{
    long long idx = (long long)blockIdx.x * 256 + threadIdx.x;   // 524288 total
    if (idx >= 524288LL) return;
    int dh = idx & 63;
    int mi = (int)((idx >> 6) & 255);
    int bh = (int)(idx >> 14);
    const float* q = g_q + ((long long)bh * SEQ + mi * LP) * DH + dh;
    const float* k = g_k + ((long long)bh * SEQ + mi * LP) * DH + dh;
    float sq = 0.f, sk = 0.f;
    #pragma unroll
    for (int j = 0; j < LP; j++) { sq += q[j * DH]; sk += k[j * DH]; }
    g_ql[idx] = sq * (1.f / LP);
    g_kl[idx] = sk * (1.f / LP);
}

// ---------------- fused attn2 = softmax(ql @ kl^T) -------------------------
// grid (4, BH); block handles 64 rows x 256 cols entirely.
__global__ void attn2_fused_kernel()
{
    extern __shared__ float sm[];
    float* QsT = sm;            // [64][68]
    float* Bt  = sm + 4352;     // [64][68]
    float* Lg  = sm + 8704;     // [64][260]
    float* inv = sm + 8704 + 16640;  // [64]

    int mt = blockIdx.x;
    int bh = blockIdx.y;
    int tid = threadIdx.x;
    int tx = tid & 15, ty = tid >> 4;

    const float* qlb = g_ql + ((long long)bh * ML + mt * 64) * DH;
    const float* klb = g_kl + (long long)bh * ML * DH;

    for (int i = tid; i < 4096; i += 256) {
        int row = i >> 6, dh = i & 63;
        QsT[dh * 68 + row] = qlb[row * 64 + dh];
    }

    for (int lt = 0; lt < 4; lt++) {
        __syncthreads();
        for (int i = tid; i < 4096; i += 256) {
            int n = i >> 6, dh = i & 63;
            Bt[dh * 68 + n] = klb[(lt * 64 + n) * 64 + dh];
        }
        __syncthreads();
        float s2[4][4] = {};
        #pragma unroll
        for (int kk = 0; kk < 64; kk++) {
            float a[4], b[4];
            #pragma unroll
            for (int i = 0; i < 4; i++) a[i] = QsT[kk * 68 + ty * 4 + i];
            #pragma unroll
            for (int j = 0; j < 4; j++) b[j] = Bt[kk * 68 + tx * 4 + j];
            #pragma unroll
            for (int i = 0; i < 4; i++)
                #pragma unroll
                for (int j = 0; j < 4; j++)
                    s2[i][j] = fmaf(a[i], b[j], s2[i][j]);
        }
        #pragma unroll
        for (int i = 0; i < 4; i++)
            #pragma unroll
            for (int j = 0; j < 4; j++)
                Lg[(ty * 4 + i) * 260 + lt * 64 + tx * 4 + j] = s2[i][j];
    }
    __syncthreads();

    // row softmax: 4 threads per row, 64 cols each
    {
        int r = tid >> 2, c0 = (tid & 3) * 64;
        float mx = -1e30f;
        for (int c = 0; c < 64; c++) mx = fmaxf(mx, Lg[r * 260 + c0 + c]);
        mx = fmaxf(mx, __shfl_xor_sync(0xffffffffu, mx, 1));
        mx = fmaxf(mx, __shfl_xor_sync(0xffffffffu, mx, 2));
        float sum = 0.f;
        for (int c = 0; c < 64; c++) {
            float e = __expf(Lg[r * 260 + c0 + c] - mx);
            Lg[r * 260 + c0 + c] = e;
            sum += e;
        }
        sum += __shfl_xor_sync(0xffffffffu, sum, 1);
        sum += __shfl_xor_sync(0xffffffffu, sum, 2);
        if ((tid & 3) == 0) inv[r] = 1.f / sum;
    }
    __syncthreads();

    float* ob = g_attn2 + ((long long)bh * ML + mt * 64) * ML;
    for (int i = tid; i < 16384; i += 256) {
        int row = i >> 8, col = i & 255;
        ob[row * 256 + col] = Lg[row * 260 + col] * inv[row];
    }
}

// ---------------- pinv scale: global max row-sum and col-sum of attn2 ----------------
__global__ void scale_init_kernel() { if (threadIdx.x < 2) g_scal[threadIdx.x] = 0.f; }

__global__ void pinv_scale_kernel()
{
    int bz = blockIdx.x;
    int j = threadIdx.x;
    const float* p = g_attn2 + (long long)bz * 65536;
    float rs = 0.f, cs = 0.f;
    for (int i = 0; i < 256; i++) { rs += p[j * 256 + i]; cs += p[i * 256 + j]; }
    atomicMax((int*)&g_scal[0], __float_as_int(rs));
    atomicMax((int*)&g_scal[1], __float_as_int(cs));
}

// ---------------- z init: z = attn2^T / (s0*s1) ----------------
__global__ void zinit_kernel()
{
    long long idx = (long long)blockIdx.x * 256 + threadIdx.x;
    if (idx >= 2097152LL) return;
    float inv = 1.f / (g_scal[0] * g_scal[1]);
    int c = (int)(idx & 255);
    int r = (int)((idx >> 8) & 255);
    long long bz = idx >> 16;
    g_z0[idx] = g_attn2[(bz << 16) + ((long long)c << 8) + r] * inv;
}

// ---------------- flash kernel: partials of softmax(ql @ k^T) @ v ----------------
// grid (SPLIT, 4, BH), 256 threads. Each block: 64 landmark rows x 1024 seq tokens.
__global__ void flash_a3v_kernel()
{
    extern __shared__ float sm[];
    float* QsT = sm;             // [64][68]
    float* Kt  = sm + 4352;
    float* Vt  = sm + 8704;
    float* Ss  = sm + 13056;
    float* msh = sm + 17408;     // [64]
    float* ssh = msh + 64;
    float* fsh = ssh + 64;

    int ks = blockIdx.x;
    int mt = blockIdx.y;
    int bh = blockIdx.z;
    int tid = threadIdx.x;
    int tx = tid & 15, ty = tid >> 4;

    const float* qlb = g_ql + ((long long)bh * ML + mt * 64) * DH;
    for (int i = tid; i < 4096; i += 256) {
        int row = i >> 6, dh = i & 63;
        QsT[dh * 68 + row] = qlb[row * 64 + dh];
    }
    if (tid < 64) { msh[tid] = -1e30f; ssh[tid] = 0.f; }
    __syncthreads();

    float acc[4][4] = {};
    const float* kb = g_k + (long long)bh * SEQ * DH;
    const float* vb = g_v + (long long)bh * SEQ * DH;
    int n_beg = ks * (SEQ / SPLIT);

    for (int nt = 0; nt < SEQ / SPLIT; nt += 64) {
        const float* kp = kb + (long long)(n_beg + nt) * DH;
        const float* vp = vb + (long long)(n_beg + nt) * DH;
        for (int i = tid; i < 4096; i += 256) {
            int n = i >> 6, dh = i & 63;
            Kt[dh * 68 + n] = kp[n * 64 + dh];
            Vt[n * 68 + dh] = vp[n * 64 + dh];
        }
        __syncthreads();

        // S = ql_tile @ k_tile^T
        float s2[4][4] = {};
        #pragma unroll
        for (int kk = 0; kk < 64; kk++) {
            float a[4], b[4];
            #pragma unroll
            for (int i = 0; i < 4; i++) a[i] = QsT[kk * 68 + ty * 4 + i];
            #pragma unroll
            for (int j = 0; j < 4; j++) b[j] = Kt[kk * 68 + tx * 4 + j];
            #pragma unroll
            for (int i = 0; i < 4; i++)
                #pragma unroll
                for (int j = 0; j < 4; j++)
                    s2[i][j] = fmaf(a[i], b[j], s2[i][j]);
        }
        #pragma unroll
        for (int i = 0; i < 4; i++)
            #pragma unroll
            for (int j = 0; j < 4; j++)
                Ss[(ty * 4 + i) * 68 + tx * 4 + j] = s2[i][j];
        __syncthreads();

        // online softmax update (4 threads per row, 16 cols each)
        {
            int r = tid >> 2, c0 = (tid & 3) * 16;
            float mx = -1e30f;
            for (int c = 0; c < 16; c++) mx = fmaxf(mx, Ss[r * 68 + c0 + c]);
            mx = fmaxf(mx, __shfl_xor_sync(0xffffffffu, mx, 1));
            mx = fmaxf(mx, __shfl_xor_sync(0xffffffffu, mx, 2));
            float mold = msh[r];
            float mnew = fmaxf(mold, mx);
            float sum = 0.f;
            for (int c = 0; c < 16; c++) {
                float e = __expf(Ss[r * 68 + c0 + c] - mnew);
                Ss[r * 68 + c0 + c] = e;
                sum += e;
            }
            sum += __shfl_xor_sync(0xffffffffu, sum, 1);
            sum += __shfl_xor_sync(0xffffffffu, sum, 2);
            if ((tid & 3) == 0) {
                float f = __expf(mold - mnew);
                ssh[r] = ssh[r] * f + sum;
                msh[r] = mnew;
                fsh[r] = f;
            }
        }
        __syncthreads();

        // rescale + acc += P @ V
        float fr[4];
        #pragma unroll
        for (int i = 0; i < 4; i++) fr[i] = fsh[ty * 4 + i];
        #pragma unroll
        for (int i = 0; i < 4; i++)
            #pragma unroll
            for (int j = 0; j < 4; j++)
                acc[i][j] *= fr[i];
        #pragma unroll
        for (int kk = 0; kk < 64; kk++) {
            float a[4], b[4];
            #pragma unroll
            for (int i = 0; i < 4; i++) a[i] = Ss[(ty * 4 + i) * 68 + kk];
            #pragma unroll
            for (int j = 0; j < 4; j++) b[j] = Vt[kk * 68 + tx * 4 + j];
            #pragma unroll
            for (int i = 0; i < 4; i++)
                #pragma unroll
                for (int j = 0; j < 4; j++)
                    acc[i][j] = fmaf(a[i], b[j], acc[i][j]);
        }
        __syncthreads();
    }

    float* po = g_part_o + (((long long)ks * BH + bh) * ML + mt * 64) * DH;
    #pragma unroll
    for (int i = 0; i < 4; i++)
        #pragma unroll
        for (int j = 0; j < 4; j++)
            po[(ty * 4 + i) * 64 + tx * 4 + j] = acc[i][j];
    if (tid < 64) {
        long long ro = ((long long)ks * BH + bh) * ML + mt * 64 + tid;
        g_part_m[ro] = msh[tid];
        g_part_s[ro] = ssh[tid];
    }
}

// ---------------- merge flash partials into a3v ----------------
__global__ void a3v_merge_kernel()
{
    long long idx = (long long)blockIdx.x * 256 + threadIdx.x;   // 524288
    if (idx >= 524288LL) return;
    int dh = (int)(idx & 63);
    long long row = idx >> 6;                                    // bh*ML + m
    float M = -1e30f;
    #pragma unroll
    for (int k = 0; k < SPLIT; k++) M = fmaxf(M, g_part_m[k * 8192 + row]);
    float num = 0.f, den = 0.f;
    #pragma unroll
    for (int k = 0; k < SPLIT; k++) {
        float w = __expf(g_part_m[k * 8192 + row] - M);
        num += g_part_o[(k * 8192 + row) * 64 + dh] * w;
        den += g_part_s[k * 8192 + row] * w;
    }
    g_a3v[idx] = num / den;
}

// ---------------- fused attn1 path: y = softmax(q @ kl^T) @ wm ----------------
// grid (128, BH); block handles 64 token rows, all 256 landmarks.
__global__ void attn1_out_kernel()
{
    extern __shared__ float sm[];
    float* QsT = sm;                 // [64][68]
    float* Bt  = sm + 4352;          // [64][68]
    float* Lg  = sm + 8704;          // [64][260]
    float* inv = sm + 8704 + 16640;  // [64]

    int st = blockIdx.x;
    int bh = blockIdx.y;
    int b = bh >> 3, h = bh & 7;
    int tid = threadIdx.x;
    int tx = tid & 15, ty = tid >> 4;

    const float* qb = g_q + ((long long)bh * SEQ + st * 64) * DH;
    for (int i = tid; i < 4096; i += 256) {
        int row = i >> 6, dh = i & 63;
        QsT[dh * 68 + row] = qb[row * 64 + dh];
    }

    const float* klb = g_kl + (long long)bh * ML * DH;
    for (int lt = 0; lt < 4; lt++) {
        __syncthreads();
        for (int i = tid; i < 4096; i += 256) {
            int n = i >> 6, dh = i & 63;
            Bt[dh * 68 + n] = klb[(lt * 64 + n) * 64 + dh];
        }
        __syncthreads();
        float s2[4][4] = {};
        #pragma unroll
        for (int kk = 0; kk < 64; kk++) {
            float a[4], bb[4];
            #pragma unroll
            for (int i = 0; i < 4; i++) a[i] = QsT[kk * 68 + ty * 4 + i];
            #pragma unroll
            for (int j = 0; j < 4; j++) bb[j] = Bt[kk * 68 + tx * 4 + j];
            #pragma unroll
            for (int i = 0; i < 4; i++)
                #pragma unroll
                for (int j = 0; j < 4; j++)
                    s2[i][j] = fmaf(a[i], bb[j], s2[i][j]);
        }
        #pragma unroll
        for (int i = 0; i < 4; i++)
            #pragma unroll
            for (int j = 0; j < 4; j++)
                Lg[(ty * 4 + i) * 260 + lt * 64 + tx * 4 + j] = s2[i][j];
    }
    __syncthreads();

    // row softmax (256 wide)
    {
        int r = tid >> 2, c0 = (tid & 3) * 64;
        float mx = -1e30f;
        for (int c = 0; c < 64; c++) mx = fmaxf(mx, Lg[r * 260 + c0 + c]);
        mx = fmaxf(mx, __shfl_xor_sync(0xffffffffu, mx, 1));
        mx = fmaxf(mx, __shfl_xor_sync(0xffffffffu, mx, 2));
        float sum = 0.f;
        for (int c = 0; c < 64; c++) {
            float e = __expf(Lg[r * 260 + c0 + c] - mx);
            Lg[r * 260 + c0 + c] = e;
            sum += e;
        }
        sum += __shfl_xor_sync(0xffffffffu, sum, 1);
        sum += __shfl_xor_sync(0xffffffffu, sum, 2);
        if ((tid & 3) == 0) inv[r] = 1.f / sum;
    }
    __syncthreads();

    // acc = P @ wm
    float acc[4][4] = {};
    const float* wmb = g_wm + (long long)bh * ML * DH;
    for (int lt = 0; lt < 4; lt++) {
        __syncthreads();
        for (int i = tid; i < 4096; i += 256) {
            int n = i >> 6, dh = i & 63;
            Bt[n * 68 + dh] = wmb[(lt * 64 + n) * 64 + dh];
        }
        __syncthreads();
        #pragma unroll
        for (int kk = 0; kk < 64; kk++) {
            float a[4], bb[4];
            #pragma unroll
            for (int i = 0; i < 4; i++) a[i] = Lg[(ty * 4 + i) * 260 + lt * 64 + kk];
            #pragma unroll
            for (int j = 0; j < 4; j++) bb[j] = Bt[kk * 68 + tx * 4 + j];
            #pragma unroll
            for (int i = 0; i < 4; i++)
                #pragma unroll
                for (int j = 0; j < 4; j++)
                    acc[i][j] = fmaf(a[i], bb[j], acc[i][j]);
        }
    }

    // write y[b][st*64+row][h*64+dh] = acc * inv[row]
    float* yb = g_y + (((long long)b * SEQ + st * 64) * NDIM) + h * DH;
    #pragma unroll
    for (int i = 0; i < 4; i++) {
        int row = ty * 4 + i;
        float iv = inv[row];
        #pragma unroll
        for (int j = 0; j < 4; j++)
            yb[(long long)row * NDIM + tx * 4 + j] = acc[i][j] * iv;
    }
}

// ---------------- depthwise conv residual (adds into g_y) ----------------
__global__ void conv_res_kernel(const float* __restrict__ convw)
{
    __shared__ float vt[96][64];
    __shared__ float wsh[KCONV];
    int bh = blockIdx.y;
    int h = bh & 7, b = bh >> 3;
    int n0 = blockIdx.x * 64;
    int tid = threadIdx.x;
    if (tid < KCONV) wsh[tid] = convw[h * KCONV + tid];
    const float* vbase = g_v + (long long)bh * SEQ * DH;
    for (int i = tid; i < 96 * 64; i += 256) {
        int r = i >> 6, dh = i & 63;
        int n = n0 + r - 16;
        vt[r][dh] = (n >= 0 && n < SEQ) ? vbase[(long long)n * DH + dh] : 0.f;
    }
    __syncthreads();
    float* ybase = g_y + ((long long)b * SEQ + n0) * NDIM + h * DH;
    for (int o = tid; o < 64 * 64; o += 256) {
        int r = o >> 6, dh = o & 63;
        float s = 0.f;
        #pragma unroll
        for (int t = 0; t < KCONV; t++) s = fmaf(wsh[t], vt[r + t][dh], s);
        ybase[(long long)r * NDIM + dh] += s;
    }
}

// ---------------- host orchestration ----------------
static float* sym(const void* p) { void* a = nullptr; cudaGetSymbolAddress(&a, p); return (float*)a; }

extern "C" void kernel_launch(void* const* d_in, const int* in_sizes, int n_in,
                              void* d_out, int out_size)
{
    const float* x      = (const float*)d_in[0];
    const float* w_qkv  = (const float*)d_in[1];
    const float* w_out  = (const float*)d_in[2];
    const float* b_out  = (const float*)d_in[3];
    const float* conv_w = (const float*)d_in[4];
    float* out = (float*)d_out;

    float* p_a2  = sym(g_attn2);
    float* p_z0  = sym(g_z0);
    float* p_z1  = sym(g_z1);
    float* p_xz  = sym(g_xz);
    float* p_t   = sym(g_t);
    float* p_u   = sym(g_u);
    float* p_a3v = sym(g_a3v);
    float* p_wm  = sym(g_wm);
    float* p_y   = sym(g_y);

    const int UNI = 1 << 30;

    static int attr_done = 0;
    if (!attr_done) {
        cudaFuncSetAttribute(attn2_fused_kernel, cudaFuncAttributeMaxDynamicSharedMemorySize, 103000);
        cudaFuncSetAttribute(attn1_out_kernel,   cudaFuncAttributeMaxDynamicSharedMemorySize, 103000);
        cudaFuncSetAttribute(flash_a3v_kernel,   cudaFuncAttributeMaxDynamicSharedMemorySize, 71000);
        attr_done = 1;
    }
    size_t big_smem = (4352 + 4352 + 16640 + 64) * sizeof(float);   // 101,632 B
    size_t fl_smem  = (4 * 4352 + 192) * sizeof(float);             // 70,400 B

    // 1. QKV projection
    qkv_gemm_kernel<<<dim3(24, 512, 1), 256>>>(x, w_qkv);

    // 2. landmark pooling
    pool_kernel<<<2048, 256>>>();

    // 3. attn2 = softmax(ql @ kl^T)   (fused)
    attn2_fused_kernel<<<dim3(4, BH), 256, big_smem>>>();

    // 4. pinv init
    scale_init_kernel<<<1, 32>>>();
    pinv_scale_kernel<<<BH, 256>>>();
    zinit_kernel<<<8192, 256>>>();

    // 5. Newton-Schulz iterations (4 dual-output GEMMs per iter)
    float* zc = p_z0;
    float* zn = p_z1;
    for (int it = 0; it < 6; it++) {
        // xz = a2@z ; t = 7I - xz
        gemm256_kernel<<<dim3(4, 4, BH), 256>>>(p_a2, zc, p_xz, p_t, 1.f, 7.f);
        // u = 15I - xz@t
        gemm256_kernel<<<dim3(4, 4, BH), 256>>>(p_xz, p_t, nullptr, p_u, 1.f, 15.f);
        // t = 13I - xz@u
        gemm256_kernel<<<dim3(4, 4, BH), 256>>>(p_xz, p_u, nullptr, p_t, 1.f, 13.f);
        // zn = 0.25 * z@t
        gemm256_kernel<<<dim3(4, 4, BH), 256>>>(zc, p_t, zn, nullptr, 0.25f, 0.f);
        float* tmp = zc; zc = zn; zn = tmp;
    }

    // 6. a3v = softmax(ql @ k^T) @ v   (flash, split over SEQ)
    flash_a3v_kernel<<<dim3(SPLIT, 4, BH), 256, fl_smem>>>();
    a3v_merge_kernel<<<2048, 256>>>();

    // 7. wm = z @ a3v : [BH, ML, DH]
    gemm_kernel<false><<<dim3(1, 4, BH), 256>>>(
        zc, p_a3v, p_wm, ML, DH, ML, ML, DH, DH,
        65536LL, (long long)ML * DH, UNI, 0, (long long)ML * DH,
        1.f, nullptr, nullptr);

    // 8. y = softmax(q @ kl^T) @ wm  (fused, scattered to [b,n,h*64+dh])
    attn1_out_kernel<<<dim3(128, BH), 256, big_smem>>>();

    // 9. depthwise conv residual (adds into y)
    conv_res_kernel<<<dim3(128, BH), 256>>>(conv_w);

    // 10. out = y @ w_out + b_out + x
    gemm_kernel<false><<<dim3(8, 512, 1), 256>>>(
        p_y, w_out, out, MTOK, NDIM, NDIM, NDIM, NDIM, NDIM,
        0, 0, UNI, 0, 0, 1.f, b_out, x);
}

// round 3
// speedup vs baseline: 2.5219x; 1.9227x over previous
#include <cuda_runtime.h>

// ---------------- problem constants ----------------
#define BATCH 4
#define SEQ   8192
#define NDIM  512
#define HEADS 8
#define DH    64
#define ML    256          // landmarks
#define LP    32           // tokens per landmark
#define BH    32           // BATCH*HEADS
#define MTOK  32768        // BATCH*SEQ
#define KCONV 33
#define SPLIT 8            // seq split for flash a3v

// ---------------- scratch (device globals; no allocation allowed) ----------------
__device__ float g_q[16777216];      // [BH, SEQ, DH]
__device__ float g_k[16777216];
__device__ float g_v[16777216];
__device__ float g_ql[524288];       // [BH, ML, DH]
__device__ float g_kl[524288];
__device__ float g_attn2[2097152];   // [BH, ML, ML]
__device__ float g_z0[2097152];
__device__ float g_z1[2097152];
__device__ float g_xz[2097152];
__device__ float g_t[2097152];
__device__ float g_u[2097152];
__device__ float g_a3v[524288];      // [BH, ML, DH]
__device__ float g_wm[524288];       // [BH, ML, DH]
__device__ float g_y[16777216];      // [MTOK, NDIM]  (b, n, h*64+dh)
__device__ float g_part_o[4194304];  // [SPLIT][BH*ML][DH]
__device__ float g_part_m[65536];    // [SPLIT][BH*ML]
__device__ float g_part_s[65536];
__device__ float g_scal[2];

// ================= TF32 tensor-core GEMM =================
__device__ __forceinline__ float tf32r(float f)
{
    unsigned u;
    asm("cvt.rna.tf32.f32 %0, %1;" : "=r"(u) : "f"(f));
    return __uint_as_float(u);
}

__device__ __forceinline__ void mma8(float* c, const unsigned* a, unsigned b0, unsigned b1)
{
    asm volatile("mma.sync.aligned.m16n8k8.row.col.f32.tf32.tf32.f32 "
                 "{%0,%1,%2,%3},{%4,%5,%6,%7},{%8,%9},{%0,%1,%2,%3};"
                 : "+f"(c[0]), "+f"(c[1]), "+f"(c[2]), "+f"(c[3])
                 : "r"(a[0]), "r"(a[1]), "r"(a[2]), "r"(a[3]), "r"(b0), "r"(b1));
}

// EPI 0: C = alpha*A@B [+bias][+resid]
// EPI 1: optional C = alpha*A@B ; optional D = diag*I - alpha*A@B   (batched via blockIdx.z)
// EPI 2: qkv scatter into g_q/g_k/g_v (q scaled by 0.125)
// Block tile 128x128, 256 threads = 8 warps (4 M x 2 N), warp tile 32x64.
// Requires: M,N multiples of 128; K multiple of 16.
template<int EPI>
__global__ void __launch_bounds__(256, 2) tgemm_kernel(
    const float* __restrict__ A, const float* __restrict__ B,
    float* __restrict__ C, float* __restrict__ D,
    int K, int lda, int ldb, int ldc,
    long long sA, long long sB, long long sC,
    float alpha, float diag,
    const float* __restrict__ bias, const float* __restrict__ resid)
{
    __shared__ float As[128][20];   // [m][k], pad 20 (20%32==4*... conflict-free frag reads)
    __shared__ float Bs[16][136];   // [k][n], pad 136 (136%32==8)

    int bz = blockIdx.z;
    A += bz * sA;
    B += bz * sB;

    const int m0 = blockIdx.y * 128;
    const int n0 = blockIdx.x * 128;
    const int tid = threadIdx.x;
    const int warp = tid >> 5, lane = tid & 31;
    const int gid = lane >> 2, tig = lane & 3;
    const int wm = warp >> 1, wn = warp & 1;   // 4 x 2 warps

    float acc[2][8][4] = {};

    for (int k0 = 0; k0 < K; k0 += 16) {
        // stage A tile: 128 rows x 16 k  (512 float4)
        #pragma unroll
        for (int it = 0; it < 2; it++) {
            int idx = tid + it * 256;
            int row = idx >> 2, kq = (idx & 3) << 2;
            float4 v = *(const float4*)&A[(long long)(m0 + row) * lda + k0 + kq];
            float4 w;
            w.x = tf32r(v.x); w.y = tf32r(v.y); w.z = tf32r(v.z); w.w = tf32r(v.w);
            *(float4*)&As[row][kq] = w;
        }
        // stage B tile: 16 k x 128 n  (512 float4)
        #pragma unroll
        for (int it = 0; it < 2; it++) {
            int idx = tid + it * 256;
            int row = idx >> 5, nq = (idx & 31) << 2;
            float4 v = *(const float4*)&B[(long long)(k0 + row) * ldb + n0 + nq];
            float4 w;
            w.x = tf32r(v.x); w.y = tf32r(v.y); w.z = tf32r(v.z); w.w = tf32r(v.w);
            *(float4*)&Bs[row][nq] = w;
        }
        __syncthreads();

        #pragma unroll
        for (int s = 0; s < 2; s++) {
            const int kb = s * 8;
            unsigned af[2][4], bf[8][2];
            #pragma unroll
            for (int mf = 0; mf < 2; mf++) {
                int r = wm * 32 + mf * 16 + gid;
                af[mf][0] = __float_as_uint(As[r][kb + tig]);
                af[mf][1] = __float_as_uint(As[r + 8][kb + tig]);
                af[mf][2] = __float_as_uint(As[r][kb + tig + 4]);
                af[mf][3] = __float_as_uint(As[r + 8][kb + tig + 4]);
            }
            #pragma unroll
            for (int nf = 0; nf < 8; nf++) {
                int c = wn * 64 + nf * 8 + gid;
                bf[nf][0] = __float_as_uint(Bs[kb + tig][c]);
                bf[nf][1] = __float_as_uint(Bs[kb + tig + 4][c]);
            }
            #pragma unroll
            for (int mf = 0; mf < 2; mf++)
                #pragma unroll
                for (int nf = 0; nf < 8; nf++)
                    mma8(acc[mf][nf], af[mf], bf[nf][0], bf[nf][1]);
        }
        __syncthreads();
    }

    // -------- epilogue --------
    #pragma unroll
    for (int mf = 0; mf < 2; mf++) {
        #pragma unroll
        for (int nf = 0; nf < 8; nf++) {
            int r0 = m0 + wm * 32 + mf * 16 + gid;
            int c0 = n0 + wn * 64 + nf * 8 + tig * 2;
            float v00 = alpha * acc[mf][nf][0];
            float v01 = alpha * acc[mf][nf][1];
            float v10 = alpha * acc[mf][nf][2];
            float v11 = alpha * acc[mf][nf][3];

            if (EPI == 0) {
                long long o0 = (long long)r0 * ldc + c0;
                long long o1 = (long long)(r0 + 8) * ldc + c0;
                if (bias)  { v00 += bias[c0]; v01 += bias[c0 + 1]; v10 += bias[c0]; v11 += bias[c0 + 1]; }
                if (resid) { v00 += resid[o0]; v01 += resid[o0 + 1]; v10 += resid[o1]; v11 += resid[o1 + 1]; }
                C[o0] = v00; C[o0 + 1] = v01;
                C[o1] = v10; C[o1 + 1] = v11;
            } else if (EPI == 1) {
                long long o0 = bz * sC + (long long)r0 * ldc + c0;
                long long o1 = bz * sC + (long long)(r0 + 8) * ldc + c0;
                if (C) { C[o0] = v00; C[o0 + 1] = v01; C[o1] = v10; C[o1 + 1] = v11; }
                if (D) {
                    D[o0]     = (r0 == c0         ? diag : 0.f) - v00;
                    D[o0 + 1] = (r0 == c0 + 1     ? diag : 0.f) - v01;
                    D[o1]     = (r0 + 8 == c0     ? diag : 0.f) - v10;
                    D[o1 + 1] = (r0 + 8 == c0 + 1 ? diag : 0.f) - v11;
                }
            } else {  // EPI == 2: qkv scatter
                int sec = c0 >> 9;
                int rem = c0 & 511;
                int h = rem >> 6, dh = rem & 63;
                #pragma unroll
                for (int rr = 0; rr < 2; rr++) {
                    int gm = r0 + rr * 8;
                    int b = gm >> 13, n = gm & 8191;
                    long long off = (((long long)(b * HEADS + h)) * SEQ + n) * DH + dh;
                    float a0 = rr ? v10 : v00;
                    float a1 = rr ? v11 : v01;
                    if (sec == 0)      { g_q[off] = a0 * 0.125f; g_q[off + 1] = a1 * 0.125f; }
                    else if (sec == 1) { g_k[off] = a0;          g_k[off + 1] = a1; }
                    else               { g_v[off] = a0;          g_v[off + 1] = a1; }
                }
            }
        }
    }
}

// ---------------- generic SIMT GEMM (only for small wm = z @ a3v) ----------------
__global__ void gemm_wm_kernel(const float* __restrict__ Zc)
{
    // per batch: C[256,64] = Z[256,256] @ a3v[256,64]
    int bz = blockIdx.z;
    const float* A = Zc + (long long)bz * 65536;
    const float* B = g_a3v + (long long)bz * ML * DH;
    float* C = g_wm + (long long)bz * ML * DH;

    __shared__ float As[16][68];
    __shared__ float Bs[16][68];

    const int tid = threadIdx.x;
    const int tx = tid & 15, ty = tid >> 4;
    const int m0 = blockIdx.y * 64;

    float acc[4][4] = {};
    for (int k0 = 0; k0 < ML; k0 += 16) {
        #pragma unroll
        for (int i = tid; i < 1024; i += 256) {
            int m = i >> 4, kk = i & 15;
            As[kk][m] = A[(m0 + m) * ML + k0 + kk];
        }
        #pragma unroll
        for (int i = tid; i < 1024; i += 256) {
            int kk = i >> 6, n = i & 63;
            Bs[kk][n] = B[(k0 + kk) * DH + n];
        }
        __syncthreads();
        #pragma unroll
        for (int kk = 0; kk < 16; kk++) {
            float a[4], bb[4];
            #pragma unroll
            for (int i = 0; i < 4; i++) a[i] = As[kk][ty * 4 + i];
            #pragma unroll
            for (int j = 0; j < 4; j++) bb[j] = Bs[kk][tx * 4 + j];
            #pragma unroll
            for (int i = 0; i < 4; i++)
                #pragma unroll
                for (int j = 0; j < 4; j++)
                    acc[i][j] = fmaf(a[i], bb[j], acc[i][j]);
        }
        __syncthreads();
    }
    #pragma unroll
    for (int i = 0; i < 4; i++)
        #pragma unroll
        for (int j = 0; j < 4; j++)
            C[(m0 + ty * 4 + i) * DH + tx * 4 + j] = acc[i][j];
}

// ---------------- landmark mean pooling ----------------
__global__ void pool_kernel()
{
    long long idx = (long long)blockIdx.x * 256 + threadIdx.x;   // 524288 total
    if (idx >= 524288LL) return;
    int dh = idx & 63;
    int mi = (int)((idx >> 6) & 255);
    int bh = (int)(idx >> 14);
    const float* q = g_q + ((long long)bh * SEQ + mi * LP) * DH + dh;
    const float* k = g_k + ((long long)bh * SEQ + mi * LP) * DH + dh;
    float sq = 0.f, sk = 0.f;
    #pragma unroll
    for (int j = 0; j < LP; j++) { sq += q[j * DH]; sk += k[j * DH]; }
    g_ql[idx] = sq * (1.f / LP);
    g_kl[idx] = sk * (1.f / LP);
}

// ---------------- fused attn2 = softmax(ql @ kl^T) -------------------------
__global__ void attn2_fused_kernel()
{
    extern __shared__ float sm[];
    float* QsT = sm;            // [64][68]
    float* Bt  = sm + 4352;     // [64][68]
    float* Lg  = sm + 8704;     // [64][260]
    float* inv = sm + 8704 + 16640;  // [64]

    int mt = blockIdx.x;
    int bh = blockIdx.y;
    int tid = threadIdx.x;
    int tx = tid & 15, ty = tid >> 4;

    const float* qlb = g_ql + ((long long)bh * ML + mt * 64) * DH;
    const float* klb = g_kl + (long long)bh * ML * DH;

    for (int i = tid; i < 4096; i += 256) {
        int row = i >> 6, dh = i & 63;
        QsT[dh * 68 + row] = qlb[row * 64 + dh];
    }

    for (int lt = 0; lt < 4; lt++) {
        __syncthreads();
        for (int i = tid; i < 4096; i += 256) {
            int n = i >> 6, dh = i & 63;
            Bt[dh * 68 + n] = klb[(lt * 64 + n) * 64 + dh];
        }
        __syncthreads();
        float s2[4][4] = {};
        #pragma unroll
        for (int kk = 0; kk < 64; kk++) {
            float a[4], b[4];
            #pragma unroll
            for (int i = 0; i < 4; i++) a[i] = QsT[kk * 68 + ty * 4 + i];
            #pragma unroll
            for (int j = 0; j < 4; j++) b[j] = Bt[kk * 68 + tx * 4 + j];
            #pragma unroll
            for (int i = 0; i < 4; i++)
                #pragma unroll
                for (int j = 0; j < 4; j++)
                    s2[i][j] = fmaf(a[i], b[j], s2[i][j]);
        }
        #pragma unroll
        for (int i = 0; i < 4; i++)
            #pragma unroll
            for (int j = 0; j < 4; j++)
                Lg[(ty * 4 + i) * 260 + lt * 64 + tx * 4 + j] = s2[i][j];
    }
    __syncthreads();

    {
        int r = tid >> 2, c0 = (tid & 3) * 64;
        float mx = -1e30f;
        for (int c = 0; c < 64; c++) mx = fmaxf(mx, Lg[r * 260 + c0 + c]);
        mx = fmaxf(mx, __shfl_xor_sync(0xffffffffu, mx, 1));
        mx = fmaxf(mx, __shfl_xor_sync(0xffffffffu, mx, 2));
        float sum = 0.f;
        for (int c = 0; c < 64; c++) {
            float e = __expf(Lg[r * 260 + c0 + c] - mx);
            Lg[r * 260 + c0 + c] = e;
            sum += e;
        }
        sum += __shfl_xor_sync(0xffffffffu, sum, 1);
        sum += __shfl_xor_sync(0xffffffffu, sum, 2);
        if ((tid & 3) == 0) inv[r] = 1.f / sum;
    }
    __syncthreads();

    float* ob = g_attn2 + ((long long)bh * ML + mt * 64) * ML;
    for (int i = tid; i < 16384; i += 256) {
        int row = i >> 8, col = i & 255;
        ob[row * 256 + col] = Lg[row * 260 + col] * inv[row];
    }
}

// ---------------- pinv scale helpers ----------------
__global__ void scale_init_kernel() { if (threadIdx.x < 2) g_scal[threadIdx.x] = 0.f; }

__global__ void pinv_scale_kernel()
{
    int bz = blockIdx.x;
    int j = threadIdx.x;
    const float* p = g_attn2 + (long long)bz * 65536;
    float rs = 0.f, cs = 0.f;
    for (int i = 0; i < 256; i++) { rs += p[j * 256 + i]; cs += p[i * 256 + j]; }
    atomicMax((int*)&g_scal[0], __float_as_int(rs));
    atomicMax((int*)&g_scal[1], __float_as_int(cs));
}

__global__ void zinit_kernel()
{
    long long idx = (long long)blockIdx.x * 256 + threadIdx.x;
    if (idx >= 2097152LL) return;
    float inv = 1.f / (g_scal[0] * g_scal[1]);
    int c = (int)(idx & 255);
    int r = (int)((idx >> 8) & 255);
    long long bz = idx >> 16;
    g_z0[idx] = g_attn2[(bz << 16) + ((long long)c << 8) + r] * inv;
}

// ---------------- flash kernel: partials of softmax(ql @ k^T) @ v ----------------
__global__ void flash_a3v_kernel()
{
    extern __shared__ float sm[];
    float* QsT = sm;             // [64][68]
    float* Kt  = sm + 4352;
    float* Vt  = sm + 8704;
    float* Ss  = sm + 13056;
    float* msh = sm + 17408;     // [64]
    float* ssh = msh + 64;
    float* fsh = ssh + 64;

    int ks = blockIdx.x;
    int mt = blockIdx.y;
    int bh = blockIdx.z;
    int tid = threadIdx.x;
    int tx = tid & 15, ty = tid >> 4;

    const float* qlb = g_ql + ((long long)bh * ML + mt * 64) * DH;
    for (int i = tid; i < 4096; i += 256) {
        int row = i >> 6, dh = i & 63;
        QsT[dh * 68 + row] = qlb[row * 64 + dh];
    }
    if (tid < 64) { msh[tid] = -1e30f; ssh[tid] = 0.f; }
    __syncthreads();

    float acc[4][4] = {};
    const float* kb = g_k + (long long)bh * SEQ * DH;
    const float* vb = g_v + (long long)bh * SEQ * DH;
    int n_beg = ks * (SEQ / SPLIT);

    for (int nt = 0; nt < SEQ / SPLIT; nt += 64) {
        const float* kp = kb + (long long)(n_beg + nt) * DH;
        const float* vp = vb + (long long)(n_beg + nt) * DH;
        for (int i = tid; i < 4096; i += 256) {
            int n = i >> 6, dh = i & 63;
            Kt[dh * 68 + n] = kp[n * 64 + dh];
            Vt[n * 68 + dh] = vp[n * 64 + dh];
        }
        __syncthreads();

        float s2[4][4] = {};
        #pragma unroll
        for (int kk = 0; kk < 64; kk++) {
            float a[4], b[4];
            #pragma unroll
            for (int i = 0; i < 4; i++) a[i] = QsT[kk * 68 + ty * 4 + i];
            #pragma unroll
            for (int j = 0; j < 4; j++) b[j] = Kt[kk * 68 + tx * 4 + j];
            #pragma unroll
            for (int i = 0; i < 4; i++)
                #pragma unroll
                for (int j = 0; j < 4; j++)
                    s2[i][j] = fmaf(a[i], b[j], s2[i][j]);
        }
        #pragma unroll
        for (int i = 0; i < 4; i++)
            #pragma unroll
            for (int j = 0; j < 4; j++)
                Ss[(ty * 4 + i) * 68 + tx * 4 + j] = s2[i][j];
        __syncthreads();

        {
            int r = tid >> 2, c0 = (tid & 3) * 16;
            float mx = -1e30f;
            for (int c = 0; c < 16; c++) mx = fmaxf(mx, Ss[r * 68 + c0 + c]);
            mx = fmaxf(mx, __shfl_xor_sync(0xffffffffu, mx, 1));
            mx = fmaxf(mx, __shfl_xor_sync(0xffffffffu, mx, 2));
            float mold = msh[r];
            float mnew = fmaxf(mold, mx);
            float sum = 0.f;
            for (int c = 0; c < 16; c++) {
                float e = __expf(Ss[r * 68 + c0 + c] - mnew);
                Ss[r * 68 + c0 + c] = e;
                sum += e;
            }
            sum += __shfl_xor_sync(0xffffffffu, sum, 1);
            sum += __shfl_xor_sync(0xffffffffu, sum, 2);
            if ((tid & 3) == 0) {
                float f = __expf(mold - mnew);
                ssh[r] = ssh[r] * f + sum;
                msh[r] = mnew;
                fsh[r] = f;
            }
        }
        __syncthreads();

        float fr[4];
        #pragma unroll
        for (int i = 0; i < 4; i++) fr[i] = fsh[ty * 4 + i];
        #pragma unroll
        for (int i = 0; i < 4; i++)
            #pragma unroll
            for (int j = 0; j < 4; j++)
                acc[i][j] *= fr[i];
        #pragma unroll
        for (int kk = 0; kk < 64; kk++) {
            float a[4], b[4];
            #pragma unroll
            for (int i = 0; i < 4; i++) a[i] = Ss[(ty * 4 + i) * 68 + kk];
            #pragma unroll
            for (int j = 0; j < 4; j++) b[j] = Vt[kk * 68 + tx * 4 + j];
            #pragma unroll
            for (int i = 0; i < 4; i++)
                #pragma unroll
                for (int j = 0; j < 4; j++)
                    acc[i][j] = fmaf(a[i], b[j], acc[i][j]);
        }
        __syncthreads();
    }

    float* po = g_part_o + (((long long)ks * BH + bh) * ML + mt * 64) * DH;
    #pragma unroll
    for (int i = 0; i < 4; i++)
        #pragma unroll
        for (int j = 0; j < 4; j++)
            po[(ty * 4 + i) * 64 + tx * 4 + j] = acc[i][j];
    if (tid < 64) {
        long long ro = ((long long)ks * BH + bh) * ML + mt * 64 + tid;
        g_part_m[ro] = msh[tid];
        g_part_s[ro] = ssh[tid];
    }
}

// ---------------- merge flash partials into a3v ----------------
__global__ void a3v_merge_kernel()
{
    long long idx = (long long)blockIdx.x * 256 + threadIdx.x;   // 524288
    if (idx >= 524288LL) return;
    int dh = (int)(idx & 63);
    long long row = idx >> 6;
    float M = -1e30f;
    #pragma unroll
    for (int k = 0; k < SPLIT; k++) M = fmaxf(M, g_part_m[k * 8192 + row]);
    float num = 0.f, den = 0.f;
    #pragma unroll
    for (int k = 0; k < SPLIT; k++) {
        float w = __expf(g_part_m[k * 8192 + row] - M);
        num += g_part_o[(k * 8192 + row) * 64 + dh] * w;
        den += g_part_s[k * 8192 + row] * w;
    }
    g_a3v[idx] = num / den;
}

// ---------------- fused attn1 path: y = softmax(q @ kl^T) @ wm ----------------
__global__ void attn1_out_kernel()
{
    extern __shared__ float sm[];
    float* QsT = sm;                 // [64][68]
    float* Bt  = sm + 4352;          // [64][68]
    float* Lg  = sm + 8704;          // [64][260]
    float* inv = sm + 8704 + 16640;  // [64]

    int st = blockIdx.x;
    int bh = blockIdx.y;
    int b = bh >> 3, h = bh & 7;
    int tid = threadIdx.x;
    int tx = tid & 15, ty = tid >> 4;

    const float* qb = g_q + ((long long)bh * SEQ + st * 64) * DH;
    for (int i = tid; i < 4096; i += 256) {
        int row = i >> 6, dh = i & 63;
        QsT[dh * 68 + row] = qb[row * 64 + dh];
    }

    const float* klb = g_kl + (long long)bh * ML * DH;
    for (int lt = 0; lt < 4; lt++) {
        __syncthreads();
        for (int i = tid; i < 4096; i += 256) {
            int n = i >> 6, dh = i & 63;
            Bt[dh * 68 + n] = klb[(lt * 64 + n) * 64 + dh];
        }
        __syncthreads();
        float s2[4][4] = {};
        #pragma unroll
        for (int kk = 0; kk < 64; kk++) {
            float a[4], bb[4];
            #pragma unroll
            for (int i = 0; i < 4; i++) a[i] = QsT[kk * 68 + ty * 4 + i];
            #pragma unroll
            for (int j = 0; j < 4; j++) bb[j] = Bt[kk * 68 + tx * 4 + j];
            #pragma unroll
            for (int i = 0; i < 4; i++)
                #pragma unroll
                for (int j = 0; j < 4; j++)
                    s2[i][j] = fmaf(a[i], bb[j], s2[i][j]);
        }
        #pragma unroll
        for (int i = 0; i < 4; i++)
            #pragma unroll
            for (int j = 0; j < 4; j++)
                Lg[(ty * 4 + i) * 260 + lt * 64 + tx * 4 + j] = s2[i][j];
    }
    __syncthreads();

    {
        int r = tid >> 2, c0 = (tid & 3) * 64;
        float mx = -1e30f;
        for (int c = 0; c < 64; c++) mx = fmaxf(mx, Lg[r * 260 + c0 + c]);
        mx = fmaxf(mx, __shfl_xor_sync(0xffffffffu, mx, 1));
        mx = fmaxf(mx, __shfl_xor_sync(0xffffffffu, mx, 2));
        float sum = 0.f;
        for (int c = 0; c < 64; c++) {
            float e = __expf(Lg[r * 260 + c0 + c] - mx);
            Lg[r * 260 + c0 + c] = e;
            sum += e;
        }
        sum += __shfl_xor_sync(0xffffffffu, sum, 1);
        sum += __shfl_xor_sync(0xffffffffu, sum, 2);
        if ((tid & 3) == 0) inv[r] = 1.f / sum;
    }
    __syncthreads();

    float acc[4][4] = {};
    const float* wmb = g_wm + (long long)bh * ML * DH;
    for (int lt = 0; lt < 4; lt++) {
        __syncthreads();
        for (int i = tid; i < 4096; i += 256) {
            int n = i >> 6, dh = i & 63;
            Bt[n * 68 + dh] = wmb[(lt * 64 + n) * 64 + dh];
        }
        __syncthreads();
        #pragma unroll
        for (int kk = 0; kk < 64; kk++) {
            float a[4], bb[4];
            #pragma unroll
            for (int i = 0; i < 4; i++) a[i] = Lg[(ty * 4 + i) * 260 + lt * 64 + kk];
            #pragma unroll
            for (int j = 0; j < 4; j++) bb[j] = Bt[kk * 68 + tx * 4 + j];
            #pragma unroll
            for (int i = 0; i < 4; i++)
                #pragma unroll
                for (int j = 0; j < 4; j++)
                    acc[i][j] = fmaf(a[i], bb[j], acc[i][j]);
        }
    }

    float* yb = g_y + (((long long)b * SEQ + st * 64) * NDIM) + h * DH;
    #pragma unroll
    for (int i = 0; i < 4; i++) {
        int row = ty * 4 + i;
        float iv = inv[row];
        #pragma unroll
        for (int j = 0; j < 4; j++)
            yb[(long long)row * NDIM + tx * 4 + j] = acc[i][j] * iv;
    }
}

// ---------------- depthwise conv residual (adds into g_y) ----------------
__global__ void conv_res_kernel(const float* __restrict__ convw)
{
    __shared__ float vt[96][64];
    __shared__ float wsh[KCONV];
    int bh = blockIdx.y;
    int h = bh & 7, b = bh >> 3;
    int n0 = blockIdx.x * 64;
    int tid = threadIdx.x;
    if (tid < KCONV) wsh[tid] = convw[h * KCONV + tid];
    const float* vbase = g_v + (long long)bh * SEQ * DH;
    for (int i = tid; i < 96 * 64; i += 256) {
        int r = i >> 6, dh = i & 63;
        int n = n0 + r - 16;
        vt[r][dh] = (n >= 0 && n < SEQ) ? vbase[(long long)n * DH + dh] : 0.f;
    }
    __syncthreads();
    float* ybase = g_y + ((long long)b * SEQ + n0) * NDIM + h * DH;
    for (int o = tid; o < 64 * 64; o += 256) {
        int r = o >> 6, dh = o & 63;
        float s = 0.f;
        #pragma unroll
        for (int t = 0; t < KCONV; t++) s = fmaf(wsh[t], vt[r + t][dh], s);
        ybase[(long long)r * NDIM + dh] += s;
    }
}

// ---------------- host orchestration ----------------
static float* sym(const void* p) { void* a = nullptr; cudaGetSymbolAddress(&a, p); return (float*)a; }

extern "C" void kernel_launch(void* const* d_in, const int* in_sizes, int n_in,
                              void* d_out, int out_size)
{
    const float* x      = (const float*)d_in[0];
    const float* w_qkv  = (const float*)d_in[1];
    const float* w_out  = (const float*)d_in[2];
    const float* b_out  = (const float*)d_in[3];
    const float* conv_w = (const float*)d_in[4];
    float* out = (float*)d_out;

    float* p_a2 = sym(g_attn2);
    float* p_z0 = sym(g_z0);
    float* p_z1 = sym(g_z1);
    float* p_xz = sym(g_xz);
    float* p_t  = sym(g_t);
    float* p_u  = sym(g_u);
    float* p_y  = sym(g_y);

    static int attr_done = 0;
    if (!attr_done) {
        cudaFuncSetAttribute(attn2_fused_kernel, cudaFuncAttributeMaxDynamicSharedMemorySize, 103000);
        cudaFuncSetAttribute(attn1_out_kernel,   cudaFuncAttributeMaxDynamicSharedMemorySize, 103000);
        cudaFuncSetAttribute(flash_a3v_kernel,   cudaFuncAttributeMaxDynamicSharedMemorySize, 71000);
        attr_done = 1;
    }
    size_t big_smem = (4352 + 4352 + 16640 + 64) * sizeof(float);
    size_t fl_smem  = (4 * 4352 + 192) * sizeof(float);

    // 1. QKV projection (tensor cores, scatter epilogue)
    tgemm_kernel<2><<<dim3(12, 256, 1), 256>>>(
        x, w_qkv, nullptr, nullptr, 512, 512, 1536, 0,
        0, 0, 0, 1.f, 0.f, nullptr, nullptr);

    // 2. landmark pooling
    pool_kernel<<<2048, 256>>>();

    // 3. attn2 = softmax(ql @ kl^T)
    attn2_fused_kernel<<<dim3(4, BH), 256, big_smem>>>();

    // 4. pinv init
    scale_init_kernel<<<1, 32>>>();
    pinv_scale_kernel<<<BH, 256>>>();
    zinit_kernel<<<8192, 256>>>();

    // 5. Newton-Schulz iterations (tensor cores, dual-output epilogue)
    float* zc = p_z0;
    float* zn = p_z1;
    for (int it = 0; it < 6; it++) {
        // xz = a2@z ; t = 7I - xz
        tgemm_kernel<1><<<dim3(2, 2, BH), 256>>>(
            p_a2, zc, p_xz, p_t, 256, 256, 256, 256,
            65536LL, 65536LL, 65536LL, 1.f, 7.f, nullptr, nullptr);
        // u = 15I - xz@t
        tgemm_kernel<1><<<dim3(2, 2, BH), 256>>>(
            p_xz, p_t, nullptr, p_u, 256, 256, 256, 256,
            65536LL, 65536LL, 65536LL, 1.f, 15.f, nullptr, nullptr);
        // t = 13I - xz@u
        tgemm_kernel<1><<<dim3(2, 2, BH), 256>>>(
            p_xz, p_u, nullptr, p_t, 256, 256, 256, 256,
            65536LL, 65536LL, 65536LL, 1.f, 13.f, nullptr, nullptr);
        // zn = 0.25 * z@t
        tgemm_kernel<1><<<dim3(2, 2, BH), 256>>>(
            zc, p_t, zn, nullptr, 256, 256, 256, 256,
            65536LL, 65536LL, 65536LL, 0.25f, 0.f, nullptr, nullptr);
        float* tmp = zc; zc = zn; zn = tmp;
    }

    // 6. a3v = softmax(ql @ k^T) @ v   (flash, split over SEQ)
    flash_a3v_kernel<<<dim3(SPLIT, 4, BH), 256, fl_smem>>>();
    a3v_merge_kernel<<<2048, 256>>>();

    // 7. wm = z @ a3v
    gemm_wm_kernel<<<dim3(1, 4, BH), 256>>>(zc);

    // 8. y = softmax(q @ kl^T) @ wm  (fused, scattered to [b,n,h*64+dh])
    attn1_out_kernel<<<dim3(128, BH), 256, big_smem>>>();

    // 9. depthwise conv residual (adds into y)
    conv_res_kernel<<<dim3(128, BH), 256>>>(conv_w);

    // 10. out = y @ w_out + b_out + x   (tensor cores)
    tgemm_kernel<0><<<dim3(4, 256, 1), 256>>>(
        p_y, w_out, out, nullptr, 512, 512, 512, 512,
        0, 0, 0, 1.f, 0.f, b_out, x);
}